// round 1
// baseline (speedup 1.0000x reference)
#include <cuda_runtime.h>
#include <cuda_bf16.h>
#include <cstdint>

#define DIM_M 8192   // B*S
#define DIM_D 2048
#define DIM_H 8192
#define K3    16384  // 2*DIM_H (hi/lo interleaved)

// ---------------- scratch (static device globals; no allocation) -------------
__device__ __nv_bfloat16 g_xq[(size_t)DIM_M * DIM_D];     // integer-valued quantized activations
__device__ float         g_scale[DIM_M];                  // amax/127 per row
__device__ __nv_bfloat16 g_wg[(size_t)DIM_H * DIM_D];     // sign(W_g)
__device__ __nv_bfloat16 g_wu[(size_t)DIM_H * DIM_D];     // sign(W_u)
__device__ __nv_bfloat16 g_wd2[(size_t)DIM_D * K3];       // sign(W_d) duplicated along K
__device__ __nv_bfloat16 g_p[(size_t)DIM_M * K3];         // p hi/lo interleaved

// ---------------- helpers ----------------------------------------------------
__device__ __forceinline__ void cp_async16(void* smem, const void* gmem) {
    uint32_t a = (uint32_t)__cvta_generic_to_shared(smem);
    asm volatile("cp.async.cg.shared.global [%0], [%1], 16;\n" :: "r"(a), "l"(gmem));
}
__device__ __forceinline__ void cp_commit() { asm volatile("cp.async.commit_group;\n"); }
__device__ __forceinline__ void cp_wait0()  { asm volatile("cp.async.wait_group 0;\n"); }

__device__ __forceinline__ uint32_t ld32(const __nv_bfloat16* p) {
    return *reinterpret_cast<const uint32_t*>(p);
}

__device__ __forceinline__ void mma_bf16(float* d, const uint32_t* a, uint32_t b0, uint32_t b1) {
    asm volatile(
        "mma.sync.aligned.m16n8k16.row.col.f32.bf16.bf16.f32 "
        "{%0,%1,%2,%3}, {%4,%5,%6,%7}, {%8,%9}, {%0,%1,%2,%3};\n"
        : "+f"(d[0]), "+f"(d[1]), "+f"(d[2]), "+f"(d[3])
        : "r"(a[0]), "r"(a[1]), "r"(a[2]), "r"(a[3]), "r"(b0), "r"(b1));
}

__device__ __forceinline__ float sgnf(float x) {
    return (x > 0.0f) ? 1.0f : ((x < 0.0f) ? -1.0f : 0.0f);
}

__device__ __forceinline__ float siluf(float x) {
    return x / (1.0f + expf(-x));
}

// block reduction over 256 threads (8 warps)
__device__ __forceinline__ float block_reduce(float v, float* sm, bool ismax) {
    int lane = threadIdx.x & 31, wid = threadIdx.x >> 5;
    #pragma unroll
    for (int o = 16; o; o >>= 1) {
        float t = __shfl_xor_sync(0xffffffffu, v, o);
        v = ismax ? fmaxf(v, t) : v + t;
    }
    if (lane == 0) sm[wid] = v;
    __syncthreads();
    float out = sm[0];
    #pragma unroll
    for (int i = 1; i < 8; i++) out = ismax ? fmaxf(out, sm[i]) : out + sm[i];
    __syncthreads();
    return out;
}

// ---------------- kernel 1: layernorm + activation quant ---------------------
__global__ __launch_bounds__(256) void quant_kernel(const float* __restrict__ x) {
    const int row = blockIdx.x, tid = threadIdx.x;
    const float4* xr = reinterpret_cast<const float4*>(x + (size_t)row * DIM_D);
    float4 a = xr[2 * tid], b = xr[2 * tid + 1];
    float v[8] = {a.x, a.y, a.z, a.w, b.x, b.y, b.z, b.w};

    __shared__ float sred[8];

    float s = 0.f;
    #pragma unroll
    for (int i = 0; i < 8; i++) s += v[i];
    s = block_reduce(s, sred, false);
    float mean = s * (1.0f / DIM_D);

    float q = 0.f;
    #pragma unroll
    for (int i = 0; i < 8; i++) { float d = v[i] - mean; q += d * d; }
    q = block_reduce(q, sred, false);
    float rstd = rsqrtf(q * (1.0f / DIM_D) + 1e-8f);

    float amax = 0.f;
    #pragma unroll
    for (int i = 0; i < 8; i++) amax = fmaxf(amax, fabsf((v[i] - mean) * rstd));
    amax = block_reduce(amax, sred, true);

    float sq = (amax > 0.f) ? (127.0f / amax) : 0.0f;

    uint32_t packed[4];
    #pragma unroll
    for (int i = 0; i < 4; i++) {
        float t0 = rintf((v[2 * i] - mean) * rstd * sq);
        float t1 = rintf((v[2 * i + 1] - mean) * rstd * sq);
        t0 = fminf(fmaxf(t0, -128.f), 127.f);
        t1 = fminf(fmaxf(t1, -128.f), 127.f);
        uint32_t lo = (uint32_t)__bfloat16_as_ushort(__float2bfloat16(t0));
        uint32_t hi = (uint32_t)__bfloat16_as_ushort(__float2bfloat16(t1));
        packed[i] = lo | (hi << 16);
    }
    uint4 out4 = make_uint4(packed[0], packed[1], packed[2], packed[3]);
    reinterpret_cast<uint4*>(g_xq + (size_t)row * DIM_D)[tid] = out4;

    if (tid == 0) g_scale[row] = amax * (1.0f / 127.0f);
}

// ---------------- kernel 2: sign conversion ----------------------------------
__global__ __launch_bounds__(256) void sign_kernel(const float4* __restrict__ w,
                                                   __nv_bfloat16* __restrict__ o, int n4) {
    int i = blockIdx.x * 256 + threadIdx.x;
    if (i >= n4) return;
    float4 v = w[i];
    uint32_t s0 = (uint32_t)__bfloat16_as_ushort(__float2bfloat16(sgnf(v.x)));
    uint32_t s1 = (uint32_t)__bfloat16_as_ushort(__float2bfloat16(sgnf(v.y)));
    uint32_t s2 = (uint32_t)__bfloat16_as_ushort(__float2bfloat16(sgnf(v.z)));
    uint32_t s3 = (uint32_t)__bfloat16_as_ushort(__float2bfloat16(sgnf(v.w)));
    uint2 out;
    out.x = s0 | (s1 << 16);
    out.y = s2 | (s3 << 16);
    reinterpret_cast<uint2*>(o)[i] = out;
}

// W_d [DIM_D x DIM_H] -> duplicated along K: o[d][2k] = o[d][2k+1] = sign(W_d[d][k])
__global__ __launch_bounds__(256) void signdup_kernel(const float4* __restrict__ w) {
    int i = blockIdx.x * 256 + threadIdx.x;   // over DIM_D*DIM_H/4 = 4194304
    float4 v = w[i];
    int j = i * 4;
    int d = j >> 13;          // /8192
    int k = j & 8191;
    uint32_t s0 = (uint32_t)__bfloat16_as_ushort(__float2bfloat16(sgnf(v.x)));
    uint32_t s1 = (uint32_t)__bfloat16_as_ushort(__float2bfloat16(sgnf(v.y)));
    uint32_t s2 = (uint32_t)__bfloat16_as_ushort(__float2bfloat16(sgnf(v.z)));
    uint32_t s3 = (uint32_t)__bfloat16_as_ushort(__float2bfloat16(sgnf(v.w)));
    uint4 out;
    out.x = s0 | (s0 << 16);
    out.y = s1 | (s1 << 16);
    out.z = s2 | (s2 << 16);
    out.w = s3 | (s3 << 16);
    *reinterpret_cast<uint4*>(g_wd2 + (size_t)d * K3 + 2 * k) = out;
}

// ---------------- GEMM tiling config -----------------------------------------
#define BM 128
#define BN 64
#define BK 32
#define ASTR 40   // padded smem row stride (bf16 elems); 80B, 16B-aligned rows

// ---------------- kernel 3: fused GEMM1 (g & u) + silu + split ---------------
__global__ __launch_bounds__(256) void gemm1_kernel() {
    __shared__ __align__(16) __nv_bfloat16 As[2][BM * ASTR];
    __shared__ __align__(16) __nv_bfloat16 Bgs[2][BN * ASTR];
    __shared__ __align__(16) __nv_bfloat16 Bus[2][BN * ASTR];

    const int tid = threadIdx.x;
    const int bn = blockIdx.x, bm = blockIdx.y;
    const int warp = tid >> 5, lane = tid & 31;
    const int wm = warp & 3, wn = warp >> 2;
    const int r = lane >> 2, c = lane & 3;

    const __nv_bfloat16* Ag  = g_xq + (size_t)bm * BM * DIM_D;
    const __nv_bfloat16* Bgg = g_wg + (size_t)bn * BN * DIM_D;
    const __nv_bfloat16* Bug = g_wu + (size_t)bn * BN * DIM_D;

    float accg[2][4][4], accu[2][4][4];
    #pragma unroll
    for (int i = 0; i < 2; i++)
        #pragma unroll
        for (int j = 0; j < 4; j++)
            #pragma unroll
            for (int e = 0; e < 4; e++) { accg[i][j][e] = 0.f; accu[i][j][e] = 0.f; }

    const int KT = DIM_D / BK;

    auto load = [&](int st, int kt) {
        int k0 = kt * BK;
        #pragma unroll
        for (int i = 0; i < 2; i++) {
            int ch = tid + i * 256;
            int arow = ch >> 2, ac = (ch & 3) * 8;
            cp_async16(&As[st][arow * ASTR + ac], Ag + (size_t)arow * DIM_D + k0 + ac);
        }
        int brow = tid >> 2, bc = (tid & 3) * 8;
        cp_async16(&Bgs[st][brow * ASTR + bc], Bgg + (size_t)brow * DIM_D + k0 + bc);
        cp_async16(&Bus[st][brow * ASTR + bc], Bug + (size_t)brow * DIM_D + k0 + bc);
        cp_commit();
    };

    load(0, 0);
    int st = 0;
    for (int kt = 0; kt < KT; kt++) {
        cp_wait0();
        __syncthreads();
        if (kt + 1 < KT) load(st ^ 1, kt + 1);
        #pragma unroll
        for (int kk = 0; kk < 2; kk++) {
            int k0 = kk * 16;
            uint32_t af[2][4];
            #pragma unroll
            for (int i = 0; i < 2; i++) {
                int row = wm * 32 + i * 16 + r;
                af[i][0] = ld32(&As[st][(row)     * ASTR + k0 + c * 2]);
                af[i][1] = ld32(&As[st][(row + 8) * ASTR + k0 + c * 2]);
                af[i][2] = ld32(&As[st][(row)     * ASTR + k0 + 8 + c * 2]);
                af[i][3] = ld32(&As[st][(row + 8) * ASTR + k0 + 8 + c * 2]);
            }
            #pragma unroll
            for (int j = 0; j < 4; j++) {
                int nrow = wn * 32 + j * 8 + r;
                uint32_t bg0 = ld32(&Bgs[st][nrow * ASTR + k0 + c * 2]);
                uint32_t bg1 = ld32(&Bgs[st][nrow * ASTR + k0 + 8 + c * 2]);
                uint32_t bu0 = ld32(&Bus[st][nrow * ASTR + k0 + c * 2]);
                uint32_t bu1 = ld32(&Bus[st][nrow * ASTR + k0 + 8 + c * 2]);
                #pragma unroll
                for (int i = 0; i < 2; i++) {
                    mma_bf16(accg[i][j], af[i], bg0, bg1);
                    mma_bf16(accu[i][j], af[i], bu0, bu1);
                }
            }
        }
        st ^= 1;
    }

    // epilogue: scale, silu, product, hi/lo split, store interleaved
    #pragma unroll
    for (int i = 0; i < 2; i++) {
        #pragma unroll
        for (int rr = 0; rr < 2; rr++) {
            int m = bm * BM + wm * 32 + i * 16 + r + rr * 8;
            float s = g_scale[m];
            size_t orow = (size_t)m * K3;
            #pragma unroll
            for (int j = 0; j < 4; j++) {
                int h = bn * BN + wn * 32 + j * 8 + c * 2;
                float cg0 = accg[i][j][rr * 2 + 0] * s;
                float cg1 = accg[i][j][rr * 2 + 1] * s;
                float cu0 = accu[i][j][rr * 2 + 0] * s;
                float cu1 = accu[i][j][rr * 2 + 1] * s;
                float p0 = siluf(cg0) * cu0;
                float p1 = siluf(cg1) * cu1;
                __nv_bfloat16 h0 = __float2bfloat16(p0);
                __nv_bfloat16 l0 = __float2bfloat16(p0 - __bfloat162float(h0));
                __nv_bfloat16 h1 = __float2bfloat16(p1);
                __nv_bfloat16 l1 = __float2bfloat16(p1 - __bfloat162float(h1));
                uint2 out;
                out.x = (uint32_t)__bfloat16_as_ushort(h0) | ((uint32_t)__bfloat16_as_ushort(l0) << 16);
                out.y = (uint32_t)__bfloat16_as_ushort(h1) | ((uint32_t)__bfloat16_as_ushort(l1) << 16);
                *reinterpret_cast<uint2*>(g_p + orow + 2 * (size_t)h) = out;
            }
        }
    }
}

// ---------------- kernel 4: GEMM3 (p @ sign(W_d)^T), K=16384 -----------------
__global__ __launch_bounds__(256) void gemm3_kernel(float* __restrict__ out) {
    __shared__ __align__(16) __nv_bfloat16 As[2][BM * ASTR];
    __shared__ __align__(16) __nv_bfloat16 Bs[2][BN * ASTR];

    const int tid = threadIdx.x;
    const int bn = blockIdx.x, bm = blockIdx.y;
    const int warp = tid >> 5, lane = tid & 31;
    const int wm = warp & 3, wn = warp >> 2;
    const int r = lane >> 2, c = lane & 3;

    const __nv_bfloat16* Ag = g_p   + (size_t)bm * BM * K3;
    const __nv_bfloat16* Bg = g_wd2 + (size_t)bn * BN * K3;

    float acc[2][4][4];
    #pragma unroll
    for (int i = 0; i < 2; i++)
        #pragma unroll
        for (int j = 0; j < 4; j++)
            #pragma unroll
            for (int e = 0; e < 4; e++) acc[i][j][e] = 0.f;

    const int KT = K3 / BK;  // 512

    auto load = [&](int st, int kt) {
        int k0 = kt * BK;
        #pragma unroll
        for (int i = 0; i < 2; i++) {
            int ch = tid + i * 256;
            int arow = ch >> 2, ac = (ch & 3) * 8;
            cp_async16(&As[st][arow * ASTR + ac], Ag + (size_t)arow * K3 + k0 + ac);
        }
        int brow = tid >> 2, bc = (tid & 3) * 8;
        cp_async16(&Bs[st][brow * ASTR + bc], Bg + (size_t)brow * K3 + k0 + bc);
        cp_commit();
    };

    load(0, 0);
    int st = 0;
    for (int kt = 0; kt < KT; kt++) {
        cp_wait0();
        __syncthreads();
        if (kt + 1 < KT) load(st ^ 1, kt + 1);
        #pragma unroll
        for (int kk = 0; kk < 2; kk++) {
            int k0 = kk * 16;
            uint32_t af[2][4];
            #pragma unroll
            for (int i = 0; i < 2; i++) {
                int row = wm * 32 + i * 16 + r;
                af[i][0] = ld32(&As[st][(row)     * ASTR + k0 + c * 2]);
                af[i][1] = ld32(&As[st][(row + 8) * ASTR + k0 + c * 2]);
                af[i][2] = ld32(&As[st][(row)     * ASTR + k0 + 8 + c * 2]);
                af[i][3] = ld32(&As[st][(row + 8) * ASTR + k0 + 8 + c * 2]);
            }
            #pragma unroll
            for (int j = 0; j < 4; j++) {
                int nrow = wn * 32 + j * 8 + r;
                uint32_t b0 = ld32(&Bs[st][nrow * ASTR + k0 + c * 2]);
                uint32_t b1 = ld32(&Bs[st][nrow * ASTR + k0 + 8 + c * 2]);
                #pragma unroll
                for (int i = 0; i < 2; i++) mma_bf16(acc[i][j], af[i], b0, b1);
            }
        }
        st ^= 1;
    }

    #pragma unroll
    for (int i = 0; i < 2; i++) {
        #pragma unroll
        for (int rr = 0; rr < 2; rr++) {
            int m = bm * BM + wm * 32 + i * 16 + r + rr * 8;
            #pragma unroll
            for (int j = 0; j < 4; j++) {
                int n = bn * BN + wn * 32 + j * 8 + c * 2;
                float2 o = make_float2(acc[i][j][rr * 2 + 0], acc[i][j][rr * 2 + 1]);
                *reinterpret_cast<float2*>(out + (size_t)m * DIM_D + n) = o;
            }
        }
    }
}

// ---------------- launch ------------------------------------------------------
extern "C" void kernel_launch(void* const* d_in, const int* in_sizes, int n_in,
                              void* d_out, int out_size) {
    const float* x  = (const float*)d_in[0];
    const float* Wg = (const float*)d_in[1];
    const float* Wu = (const float*)d_in[2];
    const float* Wd = (const float*)d_in[3];
    float* out = (float*)d_out;

    __nv_bfloat16 *wg_p, *wu_p;
    cudaGetSymbolAddress((void**)&wg_p, g_wg);
    cudaGetSymbolAddress((void**)&wu_p, g_wu);

    quant_kernel<<<DIM_M, 256>>>(x);

    const int n4 = DIM_H * DIM_D / 4;  // 4194304
    sign_kernel<<<(n4 + 255) / 256, 256>>>((const float4*)Wg, wg_p, n4);
    sign_kernel<<<(n4 + 255) / 256, 256>>>((const float4*)Wu, wu_p, n4);
    signdup_kernel<<<n4 / 256, 256>>>((const float4*)Wd);

    dim3 g1(DIM_H / BN, DIM_M / BM);   // (128, 64)
    gemm1_kernel<<<g1, 256>>>();

    dim3 g3(DIM_D / BN, DIM_M / BM);   // (32, 64)
    gemm3_kernel<<<g3, 256>>>(out);
}